// round 7
// baseline (speedup 1.0000x reference)
#include <cuda_runtime.h>
#include <math.h>

// ---------------------------------------------------------------------------
// Problem constants
//   B=16, Cin=512, P=128, Cout=512, H=W=28  -> Npix = 16*784 = 12544
//   Layout for all intermediates: [C, Npix] (channel-major, pixel index
//   p = b*784 + h*28 + w), so every conv is a clean GEMM over p.
// ---------------------------------------------------------------------------
#define NPIX 12544
#define HW   784
#define HH   28
#define WW   28

// ---------------- static device scratch (no allocations allowed) -----------
__device__ float g_xr [512 * NPIX];          // repacked input [512, NPIX]
__device__ float g_t1 [128 * NPIX];          // shift1 out
__device__ float g_y1 [128 * NPIX];          // relu(bn1(adder1))
__device__ float g_col[1152 * NPIX];         // im2col buffer (reused)
__device__ float g_t2 [128 * NPIX];          // shift2 out
__device__ float g_y2 [128 * NPIX];          // relu(bn2(adder2))
__device__ float g_t3 [512 * NPIX];          // shift3 out
__device__ float g_qw1[128 * 512];
__device__ float g_qw2[128 * 1152];
__device__ float g_qw3[512 * 128];

// ---------------------------------------------------------------------------
// Quantize shift-conv weights: q = sign(w) * 2^round(log2(|w| + 1e-8))
// (round = round-half-to-even = rintf, matching jnp.round)
// ---------------------------------------------------------------------------
__global__ void quant_k(const float* __restrict__ w, float* __restrict__ q, int n)
{
    int i = blockIdx.x * blockDim.x + threadIdx.x;
    if (i >= n) return;
    float v = w[i];
    float a = fabsf(v) + 1e-8f;
    float e = exp2f(rintf(log2f(a)));
    float s = (v > 0.f) ? 1.f : ((v < 0.f) ? -1.f : 0.f);
    q[i] = s * e;
}

// ---------------------------------------------------------------------------
// Repack x: [B,512,28,28] (NCHW) -> xr [512, NPIX], p = b*784 + hw
// ---------------------------------------------------------------------------
__global__ void repack_k(const float* __restrict__ x, float* __restrict__ xr)
{
    int i = blockIdx.x * blockDim.x + threadIdx.x;   // input index
    if (i >= 512 * NPIX) return;
    int b  = i / (512 * HW);
    int r  = i - b * (512 * HW);
    int c  = r / HW;
    int hw = r - c * HW;
    xr[c * NPIX + b * HW + hw] = x[i];
}

// ---------------------------------------------------------------------------
// im2col for 3x3 pad=1: src [128, NPIX] -> col [1152, NPIX],
// feature order k = c*9 + kh*3 + kw (matches reference _patches / w.reshape)
// ---------------------------------------------------------------------------
__global__ void im2col_k(const float* __restrict__ src, float* __restrict__ col)
{
    int idx = blockIdx.x * blockDim.x + threadIdx.x;   // over 128*NPIX
    if (idx >= 128 * NPIX) return;
    int p = idx % NPIX;
    int c = idx / NPIX;
    int b  = p / HW;
    int hw = p - b * HW;
    int h  = hw / WW;
    int w  = hw - h * WW;
    const float* s = src + (size_t)c * NPIX + b * HW;
    float* d = col + (size_t)(c * 9) * NPIX + p;
#pragma unroll
    for (int kh = 0; kh < 3; kh++) {
#pragma unroll
        for (int kw = 0; kw < 3; kw++) {
            int hh = h + kh - 1;
            int wcol = w + kw - 1;
            float v = (hh >= 0 && hh < HH && wcol >= 0 && wcol < WW)
                          ? s[hh * WW + wcol] : 0.f;
            d[(size_t)(kh * 3 + kw) * NPIX] = v;
        }
    }
}

// ---------------------------------------------------------------------------
// Tiled (adder-)GEMM.
//   A   [K, NPIX]   (k-major, pixel-contiguous)
//   W   [Co, K]     (row-major)
//   out [Co, NPIX]  (EPI 0/1)  or NCHW [B,Co,28,28] (EPI 2)
// ADDER=false:  out[o,p] =  sum_k W[o,k] * A[k,p]
// ADDER=true :  acc[o,p] =  sum_k |A[k,p] - W[o,k]|   (value is -acc)
// EPI: 0 = raw store, 1 = relu(bn(-acc)), 2 = relu(bn(-acc) + res) to NCHW
// ---------------------------------------------------------------------------
template<int BM, int BN, int BK, int TM, int TN, bool ADDER, int EPI>
__global__ __launch_bounds__(256, 2)
void gemm_k(const float* __restrict__ A, const float* __restrict__ W,
            float* __restrict__ out, int K, int Co,
            const float* __restrict__ gg, const float* __restrict__ bb,
            const float* __restrict__ mm, const float* __restrict__ vv,
            const float* __restrict__ res)
{
    __shared__ float Ws[BK][BM + 4];
    __shared__ float As[BK][BN];

    const int tid = threadIdx.x;
    const int o0  = blockIdx.y * BM;
    const int n0  = blockIdx.x * BN;
    constexpr int TX = BN / TN;           // threads along pixel dim
    const int tx = tid % TX;
    const int ty = tid / TX;

    float acc[TM][TN];
#pragma unroll
    for (int i = 0; i < TM; i++)
#pragma unroll
        for (int j = 0; j < TN; j++) acc[i][j] = 0.f;

    constexpr int WV = (BM * BK / 4) / 256;   // float4 per thread (W tile)
    constexpr int AV = (BK * BN / 4) / 256;   // float4 per thread (A tile)
    static_assert((BM * BK / 4) % 256 == 0, "W tile");
    static_assert((BK * BN / 4) % 256 == 0, "A tile");

    for (int kc = 0; kc < K; kc += BK) {
        // --- load W tile [BM x BK], store transposed Ws[k][o]
#pragma unroll
        for (int r = 0; r < WV; r++) {
            int vec = tid + r * 256;
            int o   = vec / (BK / 4);
            int kq  = vec % (BK / 4);
            float4 w4 = *reinterpret_cast<const float4*>(
                &W[(size_t)(o0 + o) * K + kc + kq * 4]);
            Ws[kq * 4 + 0][o] = w4.x;
            Ws[kq * 4 + 1][o] = w4.y;
            Ws[kq * 4 + 2][o] = w4.z;
            Ws[kq * 4 + 3][o] = w4.w;
        }
        // --- load A tile [BK x BN]
#pragma unroll
        for (int r = 0; r < AV; r++) {
            int vec = tid + r * 256;
            int k   = vec / (BN / 4);
            int nq  = vec % (BN / 4);
            *reinterpret_cast<float4*>(&As[k][nq * 4]) =
                *reinterpret_cast<const float4*>(
                    &A[(size_t)(kc + k) * NPIX + n0 + nq * 4]);
        }
        __syncthreads();

#pragma unroll
        for (int k = 0; k < BK; k++) {
            float wf[TM], af[TN];
#pragma unroll
            for (int i = 0; i < TM; i++) wf[i] = Ws[k][ty * TM + i];
#pragma unroll
            for (int j = 0; j < TN; j++) af[j] = As[k][tx * TN + j];
#pragma unroll
            for (int i = 0; i < TM; i++)
#pragma unroll
                for (int j = 0; j < TN; j++) {
                    if (ADDER) acc[i][j] += fabsf(af[j] - wf[i]);
                    else       acc[i][j] = fmaf(wf[i], af[j], acc[i][j]);
                }
        }
        __syncthreads();
    }

    // --- epilogue
#pragma unroll
    for (int i = 0; i < TM; i++) {
        int o = o0 + ty * TM + i;
        float inv = 0.f, beta = 0.f;
        if (EPI >= 1) {
            inv  = gg[o] * rsqrtf(vv[o] + 1e-5f);
            beta = bb[o] - mm[o] * inv;
        }
#pragma unroll
        for (int j = 0; j < TN; j++) {
            int p = n0 + tx * TN + j;
            float v;
            if (EPI == 0) {
                v = acc[i][j];
                out[(size_t)o * NPIX + p] = v;
            } else if (EPI == 1) {
                v = fmaf(-acc[i][j], inv, beta);
                v = fmaxf(v, 0.f);
                out[(size_t)o * NPIX + p] = v;
            } else {
                v = fmaf(-acc[i][j], inv, beta);
                v += res[(size_t)o * NPIX + p];
                v = fmaxf(v, 0.f);
                int b  = p / HW;
                int hw = p - b * HW;
                out[((size_t)(b * Co + o)) * HW + hw] = v;
            }
        }
    }
}

// ---------------------------------------------------------------------------
extern "C" void kernel_launch(void* const* d_in, const int* in_sizes, int n_in,
                              void* d_out, int out_size)
{
    const float* x   = (const float*)d_in[0];
    const float* w1s = (const float*)d_in[1];
    const float* w1a = (const float*)d_in[2];
    const float* w2s = (const float*)d_in[3];
    const float* w2a = (const float*)d_in[4];
    const float* w3s = (const float*)d_in[5];
    const float* w3a = (const float*)d_in[6];
    const float* g1 = (const float*)d_in[7];
    const float* b1 = (const float*)d_in[8];
    const float* m1 = (const float*)d_in[9];
    const float* v1 = (const float*)d_in[10];
    const float* g2 = (const float*)d_in[11];
    const float* b2 = (const float*)d_in[12];
    const float* m2 = (const float*)d_in[13];
    const float* v2 = (const float*)d_in[14];
    const float* g3 = (const float*)d_in[15];
    const float* b3 = (const float*)d_in[16];
    const float* m3 = (const float*)d_in[17];
    const float* v3 = (const float*)d_in[18];
    float* out = (float*)d_out;

    // resolve device-global scratch addresses (host-side query, capture-safe)
    float *xr, *t1, *y1, *col, *t2, *y2, *t3, *qw1, *qw2, *qw3;
    cudaGetSymbolAddress((void**)&xr,  g_xr);
    cudaGetSymbolAddress((void**)&t1,  g_t1);
    cudaGetSymbolAddress((void**)&y1,  g_y1);
    cudaGetSymbolAddress((void**)&col, g_col);
    cudaGetSymbolAddress((void**)&t2,  g_t2);
    cudaGetSymbolAddress((void**)&y2,  g_y2);
    cudaGetSymbolAddress((void**)&t3,  g_t3);
    cudaGetSymbolAddress((void**)&qw1, g_qw1);
    cudaGetSymbolAddress((void**)&qw2, g_qw2);
    cudaGetSymbolAddress((void**)&qw3, g_qw3);

    // 0) quantize shift weights + repack input
    quant_k<<<(128 * 512  + 255) / 256, 256>>>(w1s, qw1, 128 * 512);
    quant_k<<<(128 * 1152 + 255) / 256, 256>>>(w2s, qw2, 128 * 1152);
    quant_k<<<(512 * 128  + 255) / 256, 256>>>(w3s, qw3, 512 * 128);
    repack_k<<<(512 * NPIX + 255) / 256, 256>>>(x, xr);

    // 1) shift1 (1x1, 512->128):  t1 = qw1 @ xr   (BM=64 x2 for wave balance)
    gemm_k<64, 64, 32, 4, 4, false, 0><<<dim3(NPIX / 64, 2), 256>>>(
        xr, qw1, t1, 512, 128, nullptr, nullptr, nullptr, nullptr, nullptr);

    // 2) adder1 (1x1, 128->128) + bn1 + relu: y1
    gemm_k<64, 64, 32, 4, 4, true, 1><<<dim3(NPIX / 64, 2), 256>>>(
        t1, w1a, y1, 128, 128, g1, b1, m1, v1, nullptr);

    // 3) im2col(y1); shift2 (3x3, pad=1): t2 = qw2 @ col
    im2col_k<<<(128 * NPIX + 255) / 256, 256>>>(y1, col);
    gemm_k<64, 64, 32, 4, 4, false, 0><<<dim3(NPIX / 64, 2), 256>>>(
        col, qw2, t2, 1152, 128, nullptr, nullptr, nullptr, nullptr, nullptr);

    // 4) im2col(t2); adder2 (3x3, pad=1) + bn2 + relu: y2
    im2col_k<<<(128 * NPIX + 255) / 256, 256>>>(t2, col);
    gemm_k<64, 64, 32, 4, 4, true, 1><<<dim3(NPIX / 64, 2), 256>>>(
        col, w2a, y2, 1152, 128, g2, b2, m2, v2, nullptr);

    // 5) shift3 (1x1, 128->512): t3 = qw3 @ y2
    gemm_k<128, 128, 16, 8, 8, false, 0><<<dim3(NPIX / 128, 4), 256>>>(
        y2, qw3, t3, 128, 512, nullptr, nullptr, nullptr, nullptr, nullptr);

    // 6) adder3 (1x1, 512->512) + bn3 + residual + relu -> out (NCHW)
    gemm_k<128, 128, 16, 8, 8, true, 2><<<dim3(NPIX / 128, 4), 256>>>(
        t3, w3a, out, 512, 512, g3, b3, m3, v3, xr);
}